// round 10
// baseline (speedup 1.0000x reference)
#include <cuda_runtime.h>
#include <cuda_fp16.h>

#define NN 65536
#define NE 1048576
#define DIN 1024
#define DH 64
#define NC 32

// ---------------- scratch (static device globals; no allocs) ----------------
__device__ int     g_is64;
__device__ int     g_deg[NN];
__device__ int     g_scan[NN];
__device__ int     g_bsum[64];
__device__ int     g_rowptr[NN + 1];
__device__ int     g_cursor[NN];
__device__ int     g_col[NE];
__device__ float   g_dinv[NN];
__device__ __half2 g_y1h[(size_t)NN * 32];   // y1 = dinv*(x@W1), fp16 pairs
__device__ __half  g_y2h[(size_t)NN * NC];   // y2 = dinv*(h@W2), fp16
__device__ __half  g_w1h[DH * DIN];          // W1^T fp16: [n][k]

// ---------------- dtype detect + zero deg ----------------
__global__ void k_detect(const int* __restrict__ w) {
    __shared__ int s[1024];
    int t = threadIdx.x;
    int acc = 0;
    for (int i = t; i < 16384; i += 1024) acc |= w[2 * i + 1];
    s[t] = acc;
    for (int i = t; i < NN; i += 1024) g_deg[i] = 0;
    __syncthreads();
    for (int off = 512; off; off >>= 1) {
        if (t < off) s[t] |= s[t + off];
        __syncthreads();
    }
    if (t == 0) g_is64 = (s[0] == 0) ? 1 : 0;
}

__global__ void k_prep(const int* __restrict__ w) {
    int i = blockIdx.x * blockDim.x + threadIdx.x;
    if (i >= NE) return;
    int d = g_is64 ? w[2 * (NE + i)] : w[NE + i];
    atomicAdd(&g_deg[d & (NN - 1)], 1);
}

// ---------------- W1 fp16 transpose + dinv ----------------
__global__ void k_wconv(const float* __restrict__ W1) {
    int i = blockIdx.x * blockDim.x + threadIdx.x;  // i in [0, 65536)
    if (i >= DIN * DH) return;
    int k = i >> 6, n = i & 63;
    g_w1h[n * DIN + k] = __float2half_rn(W1[i]);
    g_dinv[i] = rsqrtf((float)g_deg[i] + 1.0f);   // deg counted by k_prep
}

// ---------------- GEMM1 (HMMA fp16, ldmatrix, double-buffered, occ 4) ----------------
#define SAS 40

__device__ __forceinline__ unsigned smem_u32(const void* p) {
    unsigned a;
    asm("{ .reg .u64 t; cvta.to.shared.u64 t, %1; cvt.u32.u64 %0, t; }" : "=r"(a) : "l"(p));
    return a;
}
__device__ __forceinline__ void ldsm4(unsigned* r, unsigned addr) {
    asm volatile("ldmatrix.sync.aligned.m8n8.x4.shared.b16 {%0,%1,%2,%3}, [%4];"
                 : "=r"(r[0]), "=r"(r[1]), "=r"(r[2]), "=r"(r[3]) : "r"(addr));
}
__device__ __forceinline__ void mma16816(float* d, const unsigned* a, const unsigned* b) {
    asm("mma.sync.aligned.m16n8k16.row.col.f32.f16.f16.f32 "
        "{%0,%1,%2,%3}, {%4,%5,%6,%7}, {%8,%9}, {%0,%1,%2,%3};"
        : "+f"(d[0]), "+f"(d[1]), "+f"(d[2]), "+f"(d[3])
        : "r"(a[0]), "r"(a[1]), "r"(a[2]), "r"(a[3]), "r"(b[0]), "r"(b[1]));
}

__global__ __launch_bounds__(256, 4) void k_gemm1t(const float* __restrict__ A) {
    __shared__ __half Ah[2][128][SAS], Bh[2][64][SAS];

    int tid = threadIdx.x;
    int wid = tid >> 5, lane = tid & 31;
    int wm = wid >> 1, wn = wid & 1;
    int g = lane >> 2, t = lane & 3;
    const unsigned* w1h32 = (const unsigned*)g_w1h;
    int blockRow = blockIdx.x * 128;

    int a_lrow = (lane & 15);
    int a_lcol = (lane >> 4) * 8;
    unsigned aAddr[2][2], bAddr[2];
#pragma unroll
    for (int bu = 0; bu < 2; bu++) {
#pragma unroll
        for (int mt = 0; mt < 2; mt++) {
            int r0 = wm * 32 + mt * 16;
            aAddr[bu][mt] = smem_u32(&Ah[bu][r0 + a_lrow][a_lcol]);
        }
        bAddr[bu] = smem_u32(&Bh[bu][wn * 32 + lane][0]);
    }

    int srow = tid >> 3, skq = (tid & 7) * 4;   // + i*32 rows
    int sbr  = tid >> 4, sbc = tid & 15;        // + i*16 rows

    float acc[2][4][4];
#pragma unroll
    for (int mt = 0; mt < 2; mt++)
#pragma unroll
        for (int nt = 0; nt < 4; nt++)
#pragma unroll
            for (int q = 0; q < 4; q++) acc[mt][nt][q] = 0.0f;

    float4 av[4];
    unsigned bhv[4];
#pragma unroll
    for (int i = 0; i < 4; i++) {
        av[i]  = *(const float4*)(A + (size_t)(blockRow + srow + i * 32) * DIN + skq);
        bhv[i] = w1h32[(sbr + i * 16) * (DIN / 2) + sbc];
    }
#pragma unroll
    for (int i = 0; i < 4; i++) {
        __half2 h01 = __float22half2_rn(make_float2(av[i].x, av[i].y));
        __half2 h23 = __float22half2_rn(make_float2(av[i].z, av[i].w));
        *(uint2*)&Ah[0][srow + i * 32][skq] = make_uint2(*(unsigned*)&h01, *(unsigned*)&h23);
        *(unsigned*)&Bh[0][sbr + i * 16][sbc * 2] = bhv[i];
    }
    __syncthreads();

    for (int c = 0; c < 32; c++) {
        int bu = c & 1;
        if (c + 1 < 32) {
            int kt = (c + 1) * 32;
#pragma unroll
            for (int i = 0; i < 4; i++) {
                av[i]  = *(const float4*)(A + (size_t)(blockRow + srow + i * 32) * DIN + kt + skq);
                bhv[i] = w1h32[(sbr + i * 16) * (DIN / 2) + kt / 2 + sbc];
            }
        }

#pragma unroll
        for (int kk = 0; kk < 32; kk += 16) {
            unsigned ah[2][4], bb[2][4];
#pragma unroll
            for (int mt = 0; mt < 2; mt++)
                ldsm4(ah[mt], aAddr[bu][mt] + kk * 2);
            ldsm4(bb[0], bAddr[bu] + kk * 2);
            ldsm4(bb[1], bAddr[bu] + (kk + 8) * 2);
#pragma unroll
            for (int mt = 0; mt < 2; mt++)
#pragma unroll
                for (int nt = 0; nt < 4; nt++) {
                    unsigned bfr[2] = { bb[0][nt], bb[1][nt] };
                    mma16816(acc[mt][nt], ah[mt], bfr);
                }
        }

        if (c + 1 < 32) {
#pragma unroll
            for (int i = 0; i < 4; i++) {
                __half2 h01 = __float22half2_rn(make_float2(av[i].x, av[i].y));
                __half2 h23 = __float22half2_rn(make_float2(av[i].z, av[i].w));
                *(uint2*)&Ah[bu ^ 1][srow + i * 32][skq] =
                    make_uint2(*(unsigned*)&h01, *(unsigned*)&h23);
                *(unsigned*)&Bh[bu ^ 1][sbr + i * 16][sbc * 2] = bhv[i];
            }
        }
        __syncthreads();
    }

    // epilogue: scale by dinv, store as half2
#pragma unroll
    for (int mt = 0; mt < 2; mt++) {
        int r0 = blockRow + wm * 32 + mt * 16 + g;
        int r1 = r0 + 8;
        float d0 = g_dinv[r0], d1 = g_dinv[r1];
#pragma unroll
        for (int nt = 0; nt < 4; nt++) {
            int ci = wn * 16 + nt * 4 + t;
            g_y1h[(size_t)r0 * 32 + ci] =
                __floats2half2_rn(acc[mt][nt][0] * d0, acc[mt][nt][1] * d0);
            g_y1h[(size_t)r1 * 32 + ci] =
                __floats2half2_rn(acc[mt][nt][2] * d1, acc[mt][nt][3] * d1);
        }
    }
}

// ---------------- scans / CSR ----------------
__global__ void k_scan1() {
    __shared__ int s[1024];
    int t = threadIdx.x;
    int gid = blockIdx.x * 1024 + t;
    s[t] = g_deg[gid];
    __syncthreads();
    for (int off = 1; off < 1024; off <<= 1) {
        int v = (t >= off) ? s[t - off] : 0;
        __syncthreads();
        s[t] += v;
        __syncthreads();
    }
    g_scan[gid] = s[t];
    if (t == 1023) g_bsum[blockIdx.x] = s[t];
}

__global__ void k_scan3() {
    __shared__ int sb[64];
    int t = threadIdx.x;
    if (t < 64) sb[t] = g_bsum[t];
    __syncthreads();
#pragma unroll
    for (int off = 1; off < 64; off <<= 1) {
        int v = (t < 64 && t >= off) ? sb[t - off] : 0;
        __syncthreads();
        if (t < 64) sb[t] += v;
        __syncthreads();
    }
    int i = blockIdx.x * blockDim.x + t;
    if (i >= NN) return;
    int blk = i >> 10;
    int boff = (blk ? sb[blk - 1] : 0);
    int excl = g_scan[i] - g_deg[i] + boff;
    g_rowptr[i] = excl;
    g_cursor[i] = excl;
    if (i == 0) g_rowptr[NN] = NE;
}

__global__ void k_fill(const int* __restrict__ w) {
    int i = blockIdx.x * blockDim.x + threadIdx.x;
    if (i >= NE) return;
    int s, d;
    if (g_is64) { s = w[2 * i]; d = w[2 * (NE + i)]; }
    else        { s = w[i];     d = w[NE + i]; }
    int p = atomicAdd(&g_cursor[d & (NN - 1)], 1);
    g_col[p] = s & (NN - 1);
}

// ---------------- layer-1 aggregation + relu + GEMM2 fused (warp per node) ----------------
__global__ __launch_bounds__(256) void k_agg1g2(const float* __restrict__ b1,
                                                const float* __restrict__ W2) {
    __shared__ float Ws[DH * NC];
    for (int i = threadIdx.x; i < DH * NC; i += 256) Ws[i] = W2[i];
    __syncthreads();

    int warp = (blockIdx.x * blockDim.x + threadIdx.x) >> 5;
    int lane = threadIdx.x & 31;
    if (warp >= NN) return;

    const __half2* yp = g_y1h;
    float2 a = __half22float2(yp[(size_t)warp * 32 + lane]);
    int e = g_rowptr[warp], e1 = g_rowptr[warp + 1];
    for (; e + 8 <= e1; e += 8) {
        float2 v0 = __half22float2(yp[(size_t)g_col[e]     * 32 + lane]);
        float2 v1 = __half22float2(yp[(size_t)g_col[e + 1] * 32 + lane]);
        float2 v2 = __half22float2(yp[(size_t)g_col[e + 2] * 32 + lane]);
        float2 v3 = __half22float2(yp[(size_t)g_col[e + 3] * 32 + lane]);
        float2 v4 = __half22float2(yp[(size_t)g_col[e + 4] * 32 + lane]);
        float2 v5 = __half22float2(yp[(size_t)g_col[e + 5] * 32 + lane]);
        float2 v6 = __half22float2(yp[(size_t)g_col[e + 6] * 32 + lane]);
        float2 v7 = __half22float2(yp[(size_t)g_col[e + 7] * 32 + lane]);
        a.x += ((v0.x + v1.x) + (v2.x + v3.x)) + ((v4.x + v5.x) + (v6.x + v7.x));
        a.y += ((v0.y + v1.y) + (v2.y + v3.y)) + ((v4.y + v5.y) + (v6.y + v7.y));
    }
    for (; e < e1; e++) {
        float2 v = __half22float2(yp[(size_t)g_col[e] * 32 + lane]);
        a.x += v.x; a.y += v.y;
    }

    float dv = g_dinv[warp];
    float2 bb = ((const float2*)b1)[lane];
    float hx = fmaxf(fmaf(dv, a.x, bb.x), 0.0f);
    float hy = fmaxf(fmaf(dv, a.y, bb.y), 0.0f);

    float acc2 = 0.0f;
#pragma unroll
    for (int k2 = 0; k2 < 32; k2++) {
        float sx = __shfl_sync(0xffffffffu, hx, k2);
        float sy = __shfl_sync(0xffffffffu, hy, k2);
        acc2 = fmaf(sx, Ws[(2 * k2) * NC + lane], acc2);
        acc2 = fmaf(sy, Ws[(2 * k2 + 1) * NC + lane], acc2);
    }
    g_y2h[(size_t)warp * NC + lane] = __float2half_rn(acc2 * dv);
}

// ---------------- layer-2 aggregation + log_softmax (half-warp per node) ----------------
__global__ __launch_bounds__(256) void k_agg2(const float* __restrict__ b2,
                                              float* __restrict__ out) {
    int node = (blockIdx.x * blockDim.x + threadIdx.x) >> 4;
    int l16 = threadIdx.x & 15;
    if (node >= NN) return;
    const __half2* yp = (const __half2*)g_y2h;

    float2 a = __half22float2(yp[(size_t)node * 16 + l16]);
    int e = g_rowptr[node], e1 = g_rowptr[node + 1];
    for (; e + 4 <= e1; e += 4) {
        float2 v0 = __half22float2(yp[(size_t)g_col[e]     * 16 + l16]);
        float2 v1 = __half22float2(yp[(size_t)g_col[e + 1] * 16 + l16]);
        float2 v2 = __half22float2(yp[(size_t)g_col[e + 2] * 16 + l16]);
        float2 v3 = __half22float2(yp[(size_t)g_col[e + 3] * 16 + l16]);
        a.x += (v0.x + v1.x) + (v2.x + v3.x);
        a.y += (v0.y + v1.y) + (v2.y + v3.y);
    }
    for (; e < e1; e++) {
        float2 v = __half22float2(yp[(size_t)g_col[e] * 16 + l16]);
        a.x += v.x; a.y += v.y;
    }

    float dv = g_dinv[node];
    float2 bb = ((const float2*)b2)[l16];
    float vx = fmaf(dv, a.x, bb.x);
    float vy = fmaf(dv, a.y, bb.y);

    float mx = fmaxf(vx, vy);
#pragma unroll
    for (int o = 8; o; o >>= 1) mx = fmaxf(mx, __shfl_xor_sync(0xffffffffu, mx, o));
    float sm = __expf(vx - mx) + __expf(vy - mx);
#pragma unroll
    for (int o = 8; o; o >>= 1) sm += __shfl_xor_sync(0xffffffffu, sm, o);
    float lse = mx + logf(sm);
    ((float2*)out)[(size_t)node * 16 + l16] = make_float2(vx - lse, vy - lse);
}

// ---------------- launch (gemm1t at index 3 so ncu profiles it) ----------------
extern "C" void kernel_launch(void* const* d_in, const int* in_sizes, int n_in,
                              void* d_out, int out_size) {
    const float* x  = (const float*)d_in[0];
    const int*   ei = (const int*)d_in[1];
    const float* W1 = (const float*)d_in[2];
    const float* b1 = (const float*)d_in[3];
    const float* W2 = (const float*)d_in[4];
    const float* b2 = (const float*)d_in[5];
    float* out = (float*)d_out;

    k_detect<<<1, 1024>>>(ei);
    k_prep  <<<NE / 256, 256>>>(ei);
    k_wconv <<<NN / 256, 256>>>(W1);
    k_gemm1t<<<NN / 128, 256>>>(x);
    k_scan1 <<<64, 1024>>>();
    k_scan3 <<<NN / 256, 256>>>();
    k_fill  <<<NE / 256, 256>>>(ei);
    k_agg1g2<<<NN / 8, 256>>>(b1, W2);
    k_agg2  <<<NN / 16, 256>>>(b2, out);
}

// round 11
// speedup vs baseline: 1.0901x; 1.0901x over previous
#include <cuda_runtime.h>
#include <cuda_fp16.h>

#define NN 65536
#define NE 1048576
#define DIN 1024
#define DH 64
#define NC 32

// ---------------- scratch (static device globals; no allocs) ----------------
__device__ int     g_is64;
__device__ int     g_tile;
__device__ int     g_deg[NN];
__device__ int     g_bsum[64];
__device__ int     g_flag[64];
__device__ int     g_rowptr[NN + 1];
__device__ int     g_cursor[NN];
__device__ int     g_col[NE];
__device__ float   g_dinv[NN];
__device__ __half2 g_y1h[(size_t)NN * 32];   // y1 = dinv*(x@W1), fp16 pairs
__device__ __half  g_y2h[(size_t)NN * NC];   // y2 = dinv*(h@W2), fp16
__device__ __half  g_w1h[DH * DIN];          // W1^T fp16: [n][k]

// ---------------- init: W transpose + zero deg + reset flags/tile ----------------
__global__ void k_init(const float* __restrict__ W1) {
    int i = blockIdx.x * blockDim.x + threadIdx.x;  // [0, 65536)
    int k = i >> 6, n = i & 63;
    g_w1h[n * DIN + k] = __float2half_rn(W1[i]);
    g_deg[i] = 0;
    if (i < 64) g_flag[i] = 0;
    if (i == 0) g_tile = 0;
}

// ---------------- prep: per-block dtype detect + degree count ----------------
__global__ void k_prep(const int* __restrict__ w) {
    int i = blockIdx.x * blockDim.x + threadIdx.x;
    int odd = w[2 * i + 1];                    // in-bounds under both layouts
    int any = __syncthreads_or(odd);           // any!=0 -> int32 layout
    int d = any ? w[NE + i] : w[2 * (NE + i)];
    atomicAdd(&g_deg[d & (NN - 1)], 1);
    if (i == 0) g_is64 = !any;
}

// ---------------- single-kernel scan (decoupled lookback, 64 resident blocks) ----------------
__global__ void k_scan() {
    __shared__ int s[1024];
    __shared__ int pre;
    int t = threadIdx.x, b = blockIdx.x;
    int gid = b * 1024 + t;
    int dv = g_deg[gid];
    s[t] = dv;
    if (t == 0) pre = 0;
    __syncthreads();
    for (int off = 1; off < 1024; off <<= 1) {
        int v = (t >= off) ? s[t - off] : 0;
        __syncthreads();
        s[t] += v;
        __syncthreads();
    }
    if (t == 1023) {
        g_bsum[b] = s[1023];
        __threadfence();
        atomicExch(&g_flag[b], 1);
    }
    if (t < b) {  // t in [0,b): wait for earlier blocks, accumulate their sums
        while (atomicAdd(&g_flag[t], 0) == 0) { }
        atomicAdd(&pre, atomicAdd(&g_bsum[t], 0));
    }
    __syncthreads();
    int excl = s[t] - dv + pre;
    g_rowptr[gid] = excl;
    g_cursor[gid] = excl;
    g_dinv[gid] = rsqrtf((float)dv + 1.0f);
    if (b == 63 && t == 1023) g_rowptr[NN] = NE;
}

// ---------------- GEMM1 (HMMA fp16, ldmatrix, double-buffered, occ 3, persistent) ----------------
#define SAS 40

__device__ __forceinline__ unsigned smem_u32(const void* p) {
    unsigned a;
    asm("{ .reg .u64 t; cvta.to.shared.u64 t, %1; cvt.u32.u64 %0, t; }" : "=r"(a) : "l"(p));
    return a;
}
__device__ __forceinline__ void ldsm4(unsigned* r, unsigned addr) {
    asm volatile("ldmatrix.sync.aligned.m8n8.x4.shared.b16 {%0,%1,%2,%3}, [%4];"
                 : "=r"(r[0]), "=r"(r[1]), "=r"(r[2]), "=r"(r[3]) : "r"(addr));
}
__device__ __forceinline__ void mma16816(float* d, const unsigned* a, const unsigned* b) {
    asm("mma.sync.aligned.m16n8k16.row.col.f32.f16.f16.f32 "
        "{%0,%1,%2,%3}, {%4,%5,%6,%7}, {%8,%9}, {%0,%1,%2,%3};"
        : "+f"(d[0]), "+f"(d[1]), "+f"(d[2]), "+f"(d[3])
        : "r"(a[0]), "r"(a[1]), "r"(a[2]), "r"(a[3]), "r"(b[0]), "r"(b[1]));
}

#define NTILES (NN / 128)

__global__ __launch_bounds__(256, 3) void k_gemm1t(const float* __restrict__ A) {
    __shared__ __half Ah[2][128][SAS], Bh[2][64][SAS];
    __shared__ int s_tile;

    int tid = threadIdx.x;
    int wid = tid >> 5, lane = tid & 31;
    int wm = wid >> 1, wn = wid & 1;
    int g = lane >> 2, t = lane & 3;
    const unsigned* w1h32 = (const unsigned*)g_w1h;

    int a_lrow = (lane & 15);
    int a_lcol = (lane >> 4) * 8;
    unsigned aAddr[2][2], bAddr[2];
#pragma unroll
    for (int bu = 0; bu < 2; bu++) {
#pragma unroll
        for (int mt = 0; mt < 2; mt++) {
            int r0 = wm * 32 + mt * 16;
            aAddr[bu][mt] = smem_u32(&Ah[bu][r0 + a_lrow][a_lcol]);
        }
        bAddr[bu] = smem_u32(&Bh[bu][wn * 32 + lane][0]);
    }

    int srow = tid >> 3, skq = (tid & 7) * 4;   // + i*32 rows
    int sbr  = tid >> 4, sbc = tid & 15;        // + i*16 rows

    for (;;) {
        if (tid == 0) s_tile = atomicAdd(&g_tile, 1);
        __syncthreads();
        int tile = s_tile;
        if (tile >= NTILES) break;
        int blockRow = tile * 128;

        float acc[2][4][4];
#pragma unroll
        for (int mt = 0; mt < 2; mt++)
#pragma unroll
            for (int nt = 0; nt < 4; nt++)
#pragma unroll
                for (int q = 0; q < 4; q++) acc[mt][nt][q] = 0.0f;

        float4 av[4];
        unsigned bhv[4];
#pragma unroll
        for (int i = 0; i < 4; i++) {
            av[i]  = *(const float4*)(A + (size_t)(blockRow + srow + i * 32) * DIN + skq);
            bhv[i] = w1h32[(sbr + i * 16) * (DIN / 2) + sbc];
        }
#pragma unroll
        for (int i = 0; i < 4; i++) {
            __half2 h01 = __float22half2_rn(make_float2(av[i].x, av[i].y));
            __half2 h23 = __float22half2_rn(make_float2(av[i].z, av[i].w));
            *(uint2*)&Ah[0][srow + i * 32][skq] = make_uint2(*(unsigned*)&h01, *(unsigned*)&h23);
            *(unsigned*)&Bh[0][sbr + i * 16][sbc * 2] = bhv[i];
        }
        __syncthreads();

        for (int c = 0; c < 32; c++) {
            int bu = c & 1;
            if (c + 1 < 32) {
                int kt = (c + 1) * 32;
#pragma unroll
                for (int i = 0; i < 4; i++) {
                    av[i]  = *(const float4*)(A + (size_t)(blockRow + srow + i * 32) * DIN + kt + skq);
                    bhv[i] = w1h32[(sbr + i * 16) * (DIN / 2) + kt / 2 + sbc];
                }
            }

#pragma unroll
            for (int kk = 0; kk < 32; kk += 16) {
                unsigned ah[2][4], bb[2][4];
#pragma unroll
                for (int mt = 0; mt < 2; mt++)
                    ldsm4(ah[mt], aAddr[bu][mt] + kk * 2);
                ldsm4(bb[0], bAddr[bu] + kk * 2);
                ldsm4(bb[1], bAddr[bu] + (kk + 8) * 2);
#pragma unroll
                for (int mt = 0; mt < 2; mt++)
#pragma unroll
                    for (int nt = 0; nt < 4; nt++) {
                        unsigned bfr[2] = { bb[0][nt], bb[1][nt] };
                        mma16816(acc[mt][nt], ah[mt], bfr);
                    }
            }

            if (c + 1 < 32) {
#pragma unroll
                for (int i = 0; i < 4; i++) {
                    __half2 h01 = __float22half2_rn(make_float2(av[i].x, av[i].y));
                    __half2 h23 = __float22half2_rn(make_float2(av[i].z, av[i].w));
                    *(uint2*)&Ah[bu ^ 1][srow + i * 32][skq] =
                        make_uint2(*(unsigned*)&h01, *(unsigned*)&h23);
                    *(unsigned*)&Bh[bu ^ 1][sbr + i * 16][sbc * 2] = bhv[i];
                }
            }
            __syncthreads();
        }

        // epilogue: scale by dinv, store as half2
#pragma unroll
        for (int mt = 0; mt < 2; mt++) {
            int r0 = blockRow + wm * 32 + mt * 16 + g;
            int r1 = r0 + 8;
            float d0 = g_dinv[r0], d1 = g_dinv[r1];
#pragma unroll
            for (int nt = 0; nt < 4; nt++) {
                int ci = wn * 16 + nt * 4 + t;
                g_y1h[(size_t)r0 * 32 + ci] =
                    __floats2half2_rn(acc[mt][nt][0] * d0, acc[mt][nt][1] * d0);
                g_y1h[(size_t)r1 * 32 + ci] =
                    __floats2half2_rn(acc[mt][nt][2] * d1, acc[mt][nt][3] * d1);
            }
        }
        __syncthreads();
    }
}

// ---------------- CSR fill ----------------
__global__ void k_fill(const int* __restrict__ w) {
    int i = blockIdx.x * blockDim.x + threadIdx.x;
    int s, d;
    if (g_is64) { s = w[2 * i]; d = w[2 * (NE + i)]; }
    else        { s = w[i];     d = w[NE + i]; }
    int p = atomicAdd(&g_cursor[d & (NN - 1)], 1);
    g_col[p] = s & (NN - 1);
}

// ---------------- layer-1 aggregation + relu + GEMM2 fused (warp per node) ----------------
__global__ __launch_bounds__(256) void k_agg1g2(const float* __restrict__ b1,
                                                const float* __restrict__ W2) {
    __shared__ float Ws[DH * NC];
    for (int i = threadIdx.x; i < DH * NC; i += 256) Ws[i] = W2[i];
    __syncthreads();

    int warp = (blockIdx.x * blockDim.x + threadIdx.x) >> 5;
    int lane = threadIdx.x & 31;
    if (warp >= NN) return;

    const __half2* yp = g_y1h;
    float2 a = __half22float2(yp[(size_t)warp * 32 + lane]);
    int e = g_rowptr[warp], e1 = g_rowptr[warp + 1];
    for (; e + 8 <= e1; e += 8) {
        float2 v0 = __half22float2(yp[(size_t)g_col[e]     * 32 + lane]);
        float2 v1 = __half22float2(yp[(size_t)g_col[e + 1] * 32 + lane]);
        float2 v2 = __half22float2(yp[(size_t)g_col[e + 2] * 32 + lane]);
        float2 v3 = __half22float2(yp[(size_t)g_col[e + 3] * 32 + lane]);
        float2 v4 = __half22float2(yp[(size_t)g_col[e + 4] * 32 + lane]);
        float2 v5 = __half22float2(yp[(size_t)g_col[e + 5] * 32 + lane]);
        float2 v6 = __half22float2(yp[(size_t)g_col[e + 6] * 32 + lane]);
        float2 v7 = __half22float2(yp[(size_t)g_col[e + 7] * 32 + lane]);
        a.x += ((v0.x + v1.x) + (v2.x + v3.x)) + ((v4.x + v5.x) + (v6.x + v7.x));
        a.y += ((v0.y + v1.y) + (v2.y + v3.y)) + ((v4.y + v5.y) + (v6.y + v7.y));
    }
    for (; e < e1; e++) {
        float2 v = __half22float2(yp[(size_t)g_col[e] * 32 + lane]);
        a.x += v.x; a.y += v.y;
    }

    float dv = g_dinv[warp];
    float2 bb = ((const float2*)b1)[lane];
    float hx = fmaxf(fmaf(dv, a.x, bb.x), 0.0f);
    float hy = fmaxf(fmaf(dv, a.y, bb.y), 0.0f);

    float acc2 = 0.0f;
#pragma unroll
    for (int k2 = 0; k2 < 32; k2++) {
        float sx = __shfl_sync(0xffffffffu, hx, k2);
        float sy = __shfl_sync(0xffffffffu, hy, k2);
        acc2 = fmaf(sx, Ws[(2 * k2) * NC + lane], acc2);
        acc2 = fmaf(sy, Ws[(2 * k2 + 1) * NC + lane], acc2);
    }
    g_y2h[(size_t)warp * NC + lane] = __float2half_rn(acc2 * dv);
}

// ---------------- layer-2 aggregation + log_softmax (half-warp per node) ----------------
__global__ __launch_bounds__(256) void k_agg2(const float* __restrict__ b2,
                                              float* __restrict__ out) {
    int node = (blockIdx.x * blockDim.x + threadIdx.x) >> 4;
    int l16 = threadIdx.x & 15;
    if (node >= NN) return;
    const __half2* yp = (const __half2*)g_y2h;

    float2 a = __half22float2(yp[(size_t)node * 16 + l16]);
    int e = g_rowptr[node], e1 = g_rowptr[node + 1];
    for (; e + 4 <= e1; e += 4) {
        float2 v0 = __half22float2(yp[(size_t)g_col[e]     * 16 + l16]);
        float2 v1 = __half22float2(yp[(size_t)g_col[e + 1] * 16 + l16]);
        float2 v2 = __half22float2(yp[(size_t)g_col[e + 2] * 16 + l16]);
        float2 v3 = __half22float2(yp[(size_t)g_col[e + 3] * 16 + l16]);
        a.x += (v0.x + v1.x) + (v2.x + v3.x);
        a.y += (v0.y + v1.y) + (v2.y + v3.y);
    }
    for (; e < e1; e++) {
        float2 v = __half22float2(yp[(size_t)g_col[e] * 16 + l16]);
        a.x += v.x; a.y += v.y;
    }

    float dv = g_dinv[node];
    float2 bb = ((const float2*)b2)[l16];
    float vx = fmaf(dv, a.x, bb.x);
    float vy = fmaf(dv, a.y, bb.y);

    float mx = fmaxf(vx, vy);
#pragma unroll
    for (int o = 8; o; o >>= 1) mx = fmaxf(mx, __shfl_xor_sync(0xffffffffu, mx, o));
    float sm = __expf(vx - mx) + __expf(vy - mx);
#pragma unroll
    for (int o = 8; o; o >>= 1) sm += __shfl_xor_sync(0xffffffffu, sm, o);
    float lse = mx + logf(sm);
    ((float2*)out)[(size_t)node * 16 + l16] = make_float2(vx - lse, vy - lse);
}

// ---------------- launch (7 kernels; gemm1t at index 3 for ncu) ----------------
extern "C" void kernel_launch(void* const* d_in, const int* in_sizes, int n_in,
                              void* d_out, int out_size) {
    const float* x  = (const float*)d_in[0];
    const int*   ei = (const int*)d_in[1];
    const float* W1 = (const float*)d_in[2];
    const float* b1 = (const float*)d_in[3];
    const float* W2 = (const float*)d_in[4];
    const float* b2 = (const float*)d_in[5];
    float* out = (float*)d_out;

    k_init  <<<NN / 256, 256>>>(W1);
    k_prep  <<<NE / 256, 256>>>(ei);
    k_scan  <<<64, 1024>>>();
    k_gemm1t<<<444, 256>>>(x);
    k_fill  <<<NE / 256, 256>>>(ei);
    k_agg1g2<<<NN / 8, 256>>>(b1, W2);
    k_agg2  <<<NN / 16, 256>>>(b2, out);
}

// round 12
// speedup vs baseline: 1.0934x; 1.0030x over previous
#include <cuda_runtime.h>
#include <cuda_fp16.h>

#define NN 65536
#define NE 1048576
#define DIN 1024
#define DH 64
#define NC 32

// ---------------- scratch (static device globals; no allocs) ----------------
// Self-cleaning invariants per kernel_launch invocation:
//  g_deg:  zeroed by k_scan after reading (zero-init on first run)
//  g_flag: zeroed by k_prep (same run, before k_scan)
//  g_tile: reset by k_scan (before gemm consumes it)
__device__ int     g_is64;
__device__ int     g_tile;
__device__ int     g_deg[NN];
__device__ int     g_bsum[64];
__device__ int     g_flag[64];
__device__ int     g_rowptr[NN + 1];
__device__ int     g_cursor[NN];
__device__ int     g_col[NE];
__device__ float   g_dinv[NN];
__device__ __half2 g_y1h[(size_t)NN * 32];   // y1 = dinv*(x@W1), fp16 pairs
__device__ __half  g_y2h[(size_t)NN * NC];   // y2 = dinv*(h@W2), fp16
__device__ __half  g_w1h[DH * DIN];          // W1^T fp16: [n][k]

// ---------------- prep: dtype detect + degree count + W transpose + flag reset ----------------
__global__ void k_prep(const int* __restrict__ w, const float* __restrict__ W1) {
    int i = blockIdx.x * blockDim.x + threadIdx.x;
    int odd = w[2 * i + 1];                    // in-bounds under both layouts
    int any = __syncthreads_or(odd);           // any!=0 -> int32 layout
    int d = any ? w[NE + i] : w[2 * (NE + i)];
    atomicAdd(&g_deg[d & (NN - 1)], 1);
    if (i < DIN * DH) {                        // fused W1^T fp16 conversion
        int k = i >> 6, n = i & 63;
        g_w1h[n * DIN + k] = __float2half_rn(W1[i]);
    }
    if (i < 64) g_flag[i] = 0;
    if (i == 0) g_is64 = !any;
}

// ---------------- single-kernel scan (decoupled lookback, 64 resident blocks) ----------------
__global__ void k_scan() {
    __shared__ int s[1024];
    __shared__ int pre;
    int t = threadIdx.x, b = blockIdx.x;
    int gid = b * 1024 + t;
    int dv = g_deg[gid];
    g_deg[gid] = 0;                            // self-clean for next replay
    s[t] = dv;
    if (t == 0) pre = 0;
    __syncthreads();
    for (int off = 1; off < 1024; off <<= 1) {
        int v = (t >= off) ? s[t - off] : 0;
        __syncthreads();
        s[t] += v;
        __syncthreads();
    }
    if (t == 1023) {
        g_bsum[b] = s[1023];
        __threadfence();
        atomicExch(&g_flag[b], 1);
    }
    if (t < b) {
        while (atomicAdd(&g_flag[t], 0) == 0) { }
        atomicAdd(&pre, atomicAdd(&g_bsum[t], 0));
    }
    __syncthreads();
    int excl = s[t] - dv + pre;
    g_rowptr[gid] = excl;
    g_cursor[gid] = excl;
    g_dinv[gid] = rsqrtf((float)dv + 1.0f);
    if (b == 63 && t == 1023) g_rowptr[NN] = NE;
    if (b == 0 && t == 0) g_tile = 0;          // reset tile counter for gemm
}

// ---------------- GEMM1 (HMMA fp16, ldmatrix, double-buffered, occ 3, persistent)
//                  + fused CSR fill (grid-stride, before tile loop) ----------------
#define SAS 40

__device__ __forceinline__ unsigned smem_u32(const void* p) {
    unsigned a;
    asm("{ .reg .u64 t; cvta.to.shared.u64 t, %1; cvt.u32.u64 %0, t; }" : "=r"(a) : "l"(p));
    return a;
}
__device__ __forceinline__ void ldsm4(unsigned* r, unsigned addr) {
    asm volatile("ldmatrix.sync.aligned.m8n8.x4.shared.b16 {%0,%1,%2,%3}, [%4];"
                 : "=r"(r[0]), "=r"(r[1]), "=r"(r[2]), "=r"(r[3]) : "r"(addr));
}
__device__ __forceinline__ void mma16816(float* d, const unsigned* a, const unsigned* b) {
    asm("mma.sync.aligned.m16n8k16.row.col.f32.f16.f16.f32 "
        "{%0,%1,%2,%3}, {%4,%5,%6,%7}, {%8,%9}, {%0,%1,%2,%3};"
        : "+f"(d[0]), "+f"(d[1]), "+f"(d[2]), "+f"(d[3])
        : "r"(a[0]), "r"(a[1]), "r"(a[2]), "r"(a[3]), "r"(b[0]), "r"(b[1]));
}

#define NTILES (NN / 128)
#define G1GRID 444

__global__ __launch_bounds__(256, 3) void k_gemm1t(const float* __restrict__ A,
                                                   const int* __restrict__ w) {
    __shared__ __half Ah[2][128][SAS], Bh[2][64][SAS];
    __shared__ int s_tile;

    int tid = threadIdx.x;

    // --- fused CSR fill (grid-stride over edges) ---
    {
        int is64 = g_is64;
        for (int i = blockIdx.x * 256 + tid; i < NE; i += G1GRID * 256) {
            int s, d;
            if (is64) { s = w[2 * i]; d = w[2 * (NE + i)]; }
            else      { s = w[i];     d = w[NE + i]; }
            int p = atomicAdd(&g_cursor[d & (NN - 1)], 1);
            g_col[p] = s & (NN - 1);
        }
    }

    int wid = tid >> 5, lane = tid & 31;
    int wm = wid >> 1, wn = wid & 1;
    int g = lane >> 2, t = lane & 3;
    const unsigned* w1h32 = (const unsigned*)g_w1h;

    int a_lrow = (lane & 15);
    int a_lcol = (lane >> 4) * 8;
    unsigned aAddr[2][2], bAddr[2];
#pragma unroll
    for (int bu = 0; bu < 2; bu++) {
#pragma unroll
        for (int mt = 0; mt < 2; mt++) {
            int r0 = wm * 32 + mt * 16;
            aAddr[bu][mt] = smem_u32(&Ah[bu][r0 + a_lrow][a_lcol]);
        }
        bAddr[bu] = smem_u32(&Bh[bu][wn * 32 + lane][0]);
    }

    int srow = tid >> 3, skq = (tid & 7) * 4;
    int sbr  = tid >> 4, sbc = tid & 15;

    for (;;) {
        if (tid == 0) s_tile = atomicAdd(&g_tile, 1);
        __syncthreads();
        int tile = s_tile;
        if (tile >= NTILES) break;
        int blockRow = tile * 128;

        float acc[2][4][4];
#pragma unroll
        for (int mt = 0; mt < 2; mt++)
#pragma unroll
            for (int nt = 0; nt < 4; nt++)
#pragma unroll
                for (int q = 0; q < 4; q++) acc[mt][nt][q] = 0.0f;

        float4 av[4];
        unsigned bhv[4];
#pragma unroll
        for (int i = 0; i < 4; i++) {
            av[i]  = *(const float4*)(A + (size_t)(blockRow + srow + i * 32) * DIN + skq);
            bhv[i] = w1h32[(sbr + i * 16) * (DIN / 2) + sbc];
        }
#pragma unroll
        for (int i = 0; i < 4; i++) {
            __half2 h01 = __float22half2_rn(make_float2(av[i].x, av[i].y));
            __half2 h23 = __float22half2_rn(make_float2(av[i].z, av[i].w));
            *(uint2*)&Ah[0][srow + i * 32][skq] = make_uint2(*(unsigned*)&h01, *(unsigned*)&h23);
            *(unsigned*)&Bh[0][sbr + i * 16][sbc * 2] = bhv[i];
        }
        __syncthreads();

        for (int c = 0; c < 32; c++) {
            int bu = c & 1;
            if (c + 1 < 32) {
                int kt = (c + 1) * 32;
#pragma unroll
                for (int i = 0; i < 4; i++) {
                    av[i]  = *(const float4*)(A + (size_t)(blockRow + srow + i * 32) * DIN + kt + skq);
                    bhv[i] = w1h32[(sbr + i * 16) * (DIN / 2) + kt / 2 + sbc];
                }
            }

#pragma unroll
            for (int kk = 0; kk < 32; kk += 16) {
                unsigned ah[2][4], bb[2][4];
#pragma unroll
                for (int mt = 0; mt < 2; mt++)
                    ldsm4(ah[mt], aAddr[bu][mt] + kk * 2);
                ldsm4(bb[0], bAddr[bu] + kk * 2);
                ldsm4(bb[1], bAddr[bu] + (kk + 8) * 2);
#pragma unroll
                for (int mt = 0; mt < 2; mt++)
#pragma unroll
                    for (int nt = 0; nt < 4; nt++) {
                        unsigned bfr[2] = { bb[0][nt], bb[1][nt] };
                        mma16816(acc[mt][nt], ah[mt], bfr);
                    }
            }

            if (c + 1 < 32) {
#pragma unroll
                for (int i = 0; i < 4; i++) {
                    __half2 h01 = __float22half2_rn(make_float2(av[i].x, av[i].y));
                    __half2 h23 = __float22half2_rn(make_float2(av[i].z, av[i].w));
                    *(uint2*)&Ah[bu ^ 1][srow + i * 32][skq] =
                        make_uint2(*(unsigned*)&h01, *(unsigned*)&h23);
                    *(unsigned*)&Bh[bu ^ 1][sbr + i * 16][sbc * 2] = bhv[i];
                }
            }
            __syncthreads();
        }

#pragma unroll
        for (int mt = 0; mt < 2; mt++) {
            int r0 = blockRow + wm * 32 + mt * 16 + g;
            int r1 = r0 + 8;
            float d0 = g_dinv[r0], d1 = g_dinv[r1];
#pragma unroll
            for (int nt = 0; nt < 4; nt++) {
                int ci = wn * 16 + nt * 4 + t;
                g_y1h[(size_t)r0 * 32 + ci] =
                    __floats2half2_rn(acc[mt][nt][0] * d0, acc[mt][nt][1] * d0);
                g_y1h[(size_t)r1 * 32 + ci] =
                    __floats2half2_rn(acc[mt][nt][2] * d1, acc[mt][nt][3] * d1);
            }
        }
        __syncthreads();
    }
}

// ---------------- layer-1 aggregation + relu + GEMM2 fused (warp per node) ----------------
__global__ __launch_bounds__(256) void k_agg1g2(const float* __restrict__ b1,
                                                const float* __restrict__ W2) {
    __shared__ float Ws[DH * NC];
    for (int i = threadIdx.x; i < DH * NC; i += 256) Ws[i] = W2[i];
    __syncthreads();

    int warp = (blockIdx.x * blockDim.x + threadIdx.x) >> 5;
    int lane = threadIdx.x & 31;
    if (warp >= NN) return;

    const __half2* yp = g_y1h;
    float2 a = __half22float2(yp[(size_t)warp * 32 + lane]);
    int e = g_rowptr[warp], e1 = g_rowptr[warp + 1];
    for (; e + 8 <= e1; e += 8) {
        float2 v0 = __half22float2(yp[(size_t)g_col[e]     * 32 + lane]);
        float2 v1 = __half22float2(yp[(size_t)g_col[e + 1] * 32 + lane]);
        float2 v2 = __half22float2(yp[(size_t)g_col[e + 2] * 32 + lane]);
        float2 v3 = __half22float2(yp[(size_t)g_col[e + 3] * 32 + lane]);
        float2 v4 = __half22float2(yp[(size_t)g_col[e + 4] * 32 + lane]);
        float2 v5 = __half22float2(yp[(size_t)g_col[e + 5] * 32 + lane]);
        float2 v6 = __half22float2(yp[(size_t)g_col[e + 6] * 32 + lane]);
        float2 v7 = __half22float2(yp[(size_t)g_col[e + 7] * 32 + lane]);
        a.x += ((v0.x + v1.x) + (v2.x + v3.x)) + ((v4.x + v5.x) + (v6.x + v7.x));
        a.y += ((v0.y + v1.y) + (v2.y + v3.y)) + ((v4.y + v5.y) + (v6.y + v7.y));
    }
    for (; e < e1; e++) {
        float2 v = __half22float2(yp[(size_t)g_col[e] * 32 + lane]);
        a.x += v.x; a.y += v.y;
    }

    float dv = g_dinv[warp];
    float2 bb = ((const float2*)b1)[lane];
    float hx = fmaxf(fmaf(dv, a.x, bb.x), 0.0f);
    float hy = fmaxf(fmaf(dv, a.y, bb.y), 0.0f);

    float acc2 = 0.0f;
#pragma unroll
    for (int k2 = 0; k2 < 32; k2++) {
        float sx = __shfl_sync(0xffffffffu, hx, k2);
        float sy = __shfl_sync(0xffffffffu, hy, k2);
        acc2 = fmaf(sx, Ws[(2 * k2) * NC + lane], acc2);
        acc2 = fmaf(sy, Ws[(2 * k2 + 1) * NC + lane], acc2);
    }
    g_y2h[(size_t)warp * NC + lane] = __float2half_rn(acc2 * dv);
}

// ---------------- layer-2 aggregation + log_softmax (half-warp per node) ----------------
__global__ __launch_bounds__(256) void k_agg2(const float* __restrict__ b2,
                                              float* __restrict__ out) {
    int node = (blockIdx.x * blockDim.x + threadIdx.x) >> 4;
    int l16 = threadIdx.x & 15;
    if (node >= NN) return;
    const __half2* yp = (const __half2*)g_y2h;

    float2 a = __half22float2(yp[(size_t)node * 16 + l16]);
    int e = g_rowptr[node], e1 = g_rowptr[node + 1];
    for (; e + 4 <= e1; e += 4) {
        float2 v0 = __half22float2(yp[(size_t)g_col[e]     * 16 + l16]);
        float2 v1 = __half22float2(yp[(size_t)g_col[e + 1] * 16 + l16]);
        float2 v2 = __half22float2(yp[(size_t)g_col[e + 2] * 16 + l16]);
        float2 v3 = __half22float2(yp[(size_t)g_col[e + 3] * 16 + l16]);
        a.x += (v0.x + v1.x) + (v2.x + v3.x);
        a.y += (v0.y + v1.y) + (v2.y + v3.y);
    }
    for (; e < e1; e++) {
        float2 v = __half22float2(yp[(size_t)g_col[e] * 16 + l16]);
        a.x += v.x; a.y += v.y;
    }

    float dv = g_dinv[node];
    float2 bb = ((const float2*)b2)[l16];
    float vx = fmaf(dv, a.x, bb.x);
    float vy = fmaf(dv, a.y, bb.y);

    float mx = fmaxf(vx, vy);
#pragma unroll
    for (int o = 8; o; o >>= 1) mx = fmaxf(mx, __shfl_xor_sync(0xffffffffu, mx, o));
    float sm = __expf(vx - mx) + __expf(vy - mx);
#pragma unroll
    for (int o = 8; o; o >>= 1) sm += __shfl_xor_sync(0xffffffffu, sm, o);
    float lse = mx + logf(sm);
    ((float2*)out)[(size_t)node * 16 + l16] = make_float2(vx - lse, vy - lse);
}

// ---------------- launch (5 kernels; agg1g2 at index 3 for ncu) ----------------
extern "C" void kernel_launch(void* const* d_in, const int* in_sizes, int n_in,
                              void* d_out, int out_size) {
    const float* x  = (const float*)d_in[0];
    const int*   ei = (const int*)d_in[1];
    const float* W1 = (const float*)d_in[2];
    const float* b1 = (const float*)d_in[3];
    const float* W2 = (const float*)d_in[4];
    const float* b2 = (const float*)d_in[5];
    float* out = (float*)d_out;

    k_prep  <<<NE / 256, 256>>>(ei, W1);
    k_scan  <<<64, 1024>>>();
    k_gemm1t<<<G1GRID, 256>>>(x, ei);
    k_agg1g2<<<NN / 8, 256>>>(b1, W2);
    k_agg2  <<<NN / 16, 256>>>(b2, out);
}

// round 13
// speedup vs baseline: 1.2527x; 1.1457x over previous
#include <cuda_runtime.h>
#include <cuda_fp16.h>

#define NN 65536
#define NE 1048576
#define DIN 1024
#define DH 64
#define NC 32

// ---------------- scratch (static device globals; no allocs) ----------------
// Self-cleaning per invocation: g_deg zeroed by k_scan; g_flag by k_prep; g_tile by k_scan.
__device__ int     g_is64;
__device__ int     g_tile;
__device__ int     g_deg[NN];
__device__ int     g_bsum[64];
__device__ int     g_flag[64];
__device__ int     g_rowptr[NN + 1];
__device__ int     g_cursor[NN];
__device__ int     g_col[NE];
__device__ float   g_dinv[NN];
__device__ __half2 g_y1h[(size_t)NN * 32];   // y1 = dinv*(x@W1), fp16 pairs
__device__ __half  g_y2h[(size_t)NN * NC];   // y2 = dinv*(h@W2), fp16
__device__ __half  g_w1h[DH * DIN];          // W1^T fp16: [n][k]

__device__ __forceinline__ __half2 u2h(unsigned u) { __half2 h; *(unsigned*)&h = u; return h; }

// ---------------- prep: dtype detect + degree count + W transpose + flag reset ----------------
__global__ void k_prep(const int* __restrict__ w, const float* __restrict__ W1) {
    int i = blockIdx.x * blockDim.x + threadIdx.x;
    int odd = w[2 * i + 1];
    int any = __syncthreads_or(odd);           // any!=0 -> int32 layout
    int d = any ? w[NE + i] : w[2 * (NE + i)];
    atomicAdd(&g_deg[d & (NN - 1)], 1);
    if (i < DIN * DH) {
        int k = i >> 6, n = i & 63;
        g_w1h[n * DIN + k] = __float2half_rn(W1[i]);
    }
    if (i < 64) g_flag[i] = 0;
    if (i == 0) g_is64 = !any;
}

// ---------------- single-kernel scan (decoupled lookback, 64 resident blocks) ----------------
__global__ void k_scan() {
    __shared__ int s[1024];
    __shared__ int pre;
    int t = threadIdx.x, b = blockIdx.x;
    int gid = b * 1024 + t;
    int dv = g_deg[gid];
    g_deg[gid] = 0;
    s[t] = dv;
    if (t == 0) pre = 0;
    __syncthreads();
    for (int off = 1; off < 1024; off <<= 1) {
        int v = (t >= off) ? s[t - off] : 0;
        __syncthreads();
        s[t] += v;
        __syncthreads();
    }
    if (t == 1023) {
        g_bsum[b] = s[1023];
        __threadfence();
        atomicExch(&g_flag[b], 1);
    }
    if (t < b) {
        while (atomicAdd(&g_flag[t], 0) == 0) { }
        atomicAdd(&pre, atomicAdd(&g_bsum[t], 0));
    }
    __syncthreads();
    int excl = s[t] - dv + pre;
    g_rowptr[gid] = excl;
    g_cursor[gid] = excl;
    g_dinv[gid] = rsqrtf((float)dv + 1.0f);
    if (b == 63 && t == 1023) g_rowptr[NN] = NE;
    if (b == 0 && t == 0) g_tile = 0;
}

// ---------------- GEMM1 (HMMA fp16, ldmatrix, double-buffered, occ 3, persistent)
//                  + fused CSR fill ----------------
#define SAS 40

__device__ __forceinline__ unsigned smem_u32(const void* p) {
    unsigned a;
    asm("{ .reg .u64 t; cvta.to.shared.u64 t, %1; cvt.u32.u64 %0, t; }" : "=r"(a) : "l"(p));
    return a;
}
__device__ __forceinline__ void ldsm4(unsigned* r, unsigned addr) {
    asm volatile("ldmatrix.sync.aligned.m8n8.x4.shared.b16 {%0,%1,%2,%3}, [%4];"
                 : "=r"(r[0]), "=r"(r[1]), "=r"(r[2]), "=r"(r[3]) : "r"(addr));
}
__device__ __forceinline__ void mma16816(float* d, const unsigned* a, const unsigned* b) {
    asm("mma.sync.aligned.m16n8k16.row.col.f32.f16.f16.f32 "
        "{%0,%1,%2,%3}, {%4,%5,%6,%7}, {%8,%9}, {%0,%1,%2,%3};"
        : "+f"(d[0]), "+f"(d[1]), "+f"(d[2]), "+f"(d[3])
        : "r"(a[0]), "r"(a[1]), "r"(a[2]), "r"(a[3]), "r"(b[0]), "r"(b[1]));
}

#define NTILES (NN / 128)
#define G1GRID 444

__global__ __launch_bounds__(256, 3) void k_gemm1t(const float* __restrict__ A,
                                                   const int* __restrict__ w) {
    __shared__ __half Ah[2][128][SAS], Bh[2][64][SAS];
    __shared__ int s_tile;

    int tid = threadIdx.x;

    // --- fused CSR fill (grid-stride over edges) ---
    {
        int is64 = g_is64;
        for (int i = blockIdx.x * 256 + tid; i < NE; i += G1GRID * 256) {
            int s, d;
            if (is64) { s = w[2 * i]; d = w[2 * (NE + i)]; }
            else      { s = w[i];     d = w[NE + i]; }
            int p = atomicAdd(&g_cursor[d & (NN - 1)], 1);
            g_col[p] = s & (NN - 1);
        }
    }

    int wid = tid >> 5, lane = tid & 31;
    int wm = wid >> 1, wn = wid & 1;
    int g = lane >> 2, t = lane & 3;
    const unsigned* w1h32 = (const unsigned*)g_w1h;

    int a_lrow = (lane & 15);
    int a_lcol = (lane >> 4) * 8;
    unsigned aAddr[2][2], bAddr[2];
#pragma unroll
    for (int bu = 0; bu < 2; bu++) {
#pragma unroll
        for (int mt = 0; mt < 2; mt++) {
            int r0 = wm * 32 + mt * 16;
            aAddr[bu][mt] = smem_u32(&Ah[bu][r0 + a_lrow][a_lcol]);
        }
        bAddr[bu] = smem_u32(&Bh[bu][wn * 32 + lane][0]);
    }

    int srow = tid >> 3, skq = (tid & 7) * 4;
    int sbr  = tid >> 4, sbc = tid & 15;

    for (;;) {
        if (tid == 0) s_tile = atomicAdd(&g_tile, 1);
        __syncthreads();
        int tile = s_tile;
        if (tile >= NTILES) break;
        int blockRow = tile * 128;

        float acc[2][4][4];
#pragma unroll
        for (int mt = 0; mt < 2; mt++)
#pragma unroll
            for (int nt = 0; nt < 4; nt++)
#pragma unroll
                for (int q = 0; q < 4; q++) acc[mt][nt][q] = 0.0f;

        float4 av[4];
        unsigned bhv[4];
#pragma unroll
        for (int i = 0; i < 4; i++) {
            av[i]  = *(const float4*)(A + (size_t)(blockRow + srow + i * 32) * DIN + skq);
            bhv[i] = w1h32[(sbr + i * 16) * (DIN / 2) + sbc];
        }
#pragma unroll
        for (int i = 0; i < 4; i++) {
            __half2 h01 = __float22half2_rn(make_float2(av[i].x, av[i].y));
            __half2 h23 = __float22half2_rn(make_float2(av[i].z, av[i].w));
            *(uint2*)&Ah[0][srow + i * 32][skq] = make_uint2(*(unsigned*)&h01, *(unsigned*)&h23);
            *(unsigned*)&Bh[0][sbr + i * 16][sbc * 2] = bhv[i];
        }
        __syncthreads();

        for (int c = 0; c < 32; c++) {
            int bu = c & 1;
            if (c + 1 < 32) {
                int kt = (c + 1) * 32;
#pragma unroll
                for (int i = 0; i < 4; i++) {
                    av[i]  = *(const float4*)(A + (size_t)(blockRow + srow + i * 32) * DIN + kt + skq);
                    bhv[i] = w1h32[(sbr + i * 16) * (DIN / 2) + kt / 2 + sbc];
                }
            }

#pragma unroll
            for (int kk = 0; kk < 32; kk += 16) {
                unsigned ah[2][4], bb[2][4];
#pragma unroll
                for (int mt = 0; mt < 2; mt++)
                    ldsm4(ah[mt], aAddr[bu][mt] + kk * 2);
                ldsm4(bb[0], bAddr[bu] + kk * 2);
                ldsm4(bb[1], bAddr[bu] + (kk + 8) * 2);
#pragma unroll
                for (int mt = 0; mt < 2; mt++)
#pragma unroll
                    for (int nt = 0; nt < 4; nt++) {
                        unsigned bfr[2] = { bb[0][nt], bb[1][nt] };
                        mma16816(acc[mt][nt], ah[mt], bfr);
                    }
            }

            if (c + 1 < 32) {
#pragma unroll
                for (int i = 0; i < 4; i++) {
                    __half2 h01 = __float22half2_rn(make_float2(av[i].x, av[i].y));
                    __half2 h23 = __float22half2_rn(make_float2(av[i].z, av[i].w));
                    *(uint2*)&Ah[bu ^ 1][srow + i * 32][skq] =
                        make_uint2(*(unsigned*)&h01, *(unsigned*)&h23);
                    *(unsigned*)&Bh[bu ^ 1][sbr + i * 16][sbc * 2] = bhv[i];
                }
            }
            __syncthreads();
        }

#pragma unroll
        for (int mt = 0; mt < 2; mt++) {
            int r0 = blockRow + wm * 32 + mt * 16 + g;
            int r1 = r0 + 8;
            float d0 = g_dinv[r0], d1 = g_dinv[r1];
#pragma unroll
            for (int nt = 0; nt < 4; nt++) {
                int ci = wn * 16 + nt * 4 + t;
                g_y1h[(size_t)r0 * 32 + ci] =
                    __floats2half2_rn(acc[mt][nt][0] * d0, acc[mt][nt][1] * d0);
                g_y1h[(size_t)r1 * 32 + ci] =
                    __floats2half2_rn(acc[mt][nt][2] * d1, acc[mt][nt][3] * d1);
            }
        }
        __syncthreads();
    }
}

// ---------------- layer-1 aggregation + relu + GEMM2 fused (8 lanes per node) ----------------
__global__ __launch_bounds__(256) void k_agg1g2(const float* __restrict__ b1,
                                                const float* __restrict__ W2) {
    __shared__ float Ws[DH * NC];
    for (int i = threadIdx.x; i < DH * NC; i += 256) Ws[i] = W2[i];
    __syncthreads();

    int gid = blockIdx.x * 256 + threadIdx.x;
    int node = gid >> 3;
    int l8 = threadIdx.x & 7;
    const uint4* yp4 = (const uint4*)g_y1h;    // row = 8 uint4

    uint4 sv = yp4[(size_t)node * 8 + l8];
    __half2 a0 = u2h(sv.x), a1 = u2h(sv.y), a2 = u2h(sv.z), a3 = u2h(sv.w);

    int e = g_rowptr[node], e1 = g_rowptr[node + 1];
    for (; e + 4 <= e1; e += 4) {
        uint4 v0 = yp4[(size_t)g_col[e]     * 8 + l8];
        uint4 v1 = yp4[(size_t)g_col[e + 1] * 8 + l8];
        uint4 v2 = yp4[(size_t)g_col[e + 2] * 8 + l8];
        uint4 v3 = yp4[(size_t)g_col[e + 3] * 8 + l8];
        a0 = __hadd2(a0, __hadd2(__hadd2(u2h(v0.x), u2h(v1.x)), __hadd2(u2h(v2.x), u2h(v3.x))));
        a1 = __hadd2(a1, __hadd2(__hadd2(u2h(v0.y), u2h(v1.y)), __hadd2(u2h(v2.y), u2h(v3.y))));
        a2 = __hadd2(a2, __hadd2(__hadd2(u2h(v0.z), u2h(v1.z)), __hadd2(u2h(v2.z), u2h(v3.z))));
        a3 = __hadd2(a3, __hadd2(__hadd2(u2h(v0.w), u2h(v1.w)), __hadd2(u2h(v2.w), u2h(v3.w))));
    }
    for (; e < e1; e++) {
        uint4 v = yp4[(size_t)g_col[e] * 8 + l8];
        a0 = __hadd2(a0, u2h(v.x));
        a1 = __hadd2(a1, u2h(v.y));
        a2 = __hadd2(a2, u2h(v.z));
        a3 = __hadd2(a3, u2h(v.w));
    }

    float dv = g_dinv[node];
    float4 bb0 = ((const float4*)b1)[l8 * 2];
    float4 bb1 = ((const float4*)b1)[l8 * 2 + 1];
    float2 f0 = __half22float2(a0), f1 = __half22float2(a1);
    float2 f2 = __half22float2(a2), f3 = __half22float2(a3);
    float h[8];
    h[0] = fmaxf(fmaf(dv, f0.x, bb0.x), 0.0f);
    h[1] = fmaxf(fmaf(dv, f0.y, bb0.y), 0.0f);
    h[2] = fmaxf(fmaf(dv, f1.x, bb0.z), 0.0f);
    h[3] = fmaxf(fmaf(dv, f1.y, bb0.w), 0.0f);
    h[4] = fmaxf(fmaf(dv, f2.x, bb1.x), 0.0f);
    h[5] = fmaxf(fmaf(dv, f2.y, bb1.y), 0.0f);
    h[6] = fmaxf(fmaf(dv, f3.x, bb1.z), 0.0f);
    h[7] = fmaxf(fmaf(dv, f3.y, bb1.w), 0.0f);

    // fused GEMM2: lane computes classes l8, l8+8, l8+16, l8+24
    float acc[4] = {0.0f, 0.0f, 0.0f, 0.0f};
#pragma unroll
    for (int j = 0; j < 8; j++) {
#pragma unroll
        for (int s = 0; s < 8; s++) {
            float hb = __shfl_sync(0xffffffffu, h[j], s, 8);
            int k = s * 8 + j;
            acc[0] = fmaf(hb, Ws[k * NC + l8], acc[0]);
            acc[1] = fmaf(hb, Ws[k * NC + l8 + 8], acc[1]);
            acc[2] = fmaf(hb, Ws[k * NC + l8 + 16], acc[2]);
            acc[3] = fmaf(hb, Ws[k * NC + l8 + 24], acc[3]);
        }
    }
    __half* y2 = g_y2h + (size_t)node * NC;
    y2[l8]      = __float2half_rn(acc[0] * dv);
    y2[l8 + 8]  = __float2half_rn(acc[1] * dv);
    y2[l8 + 16] = __float2half_rn(acc[2] * dv);
    y2[l8 + 24] = __float2half_rn(acc[3] * dv);
}

// ---------------- layer-2 aggregation + log_softmax (8 lanes per node) ----------------
__global__ __launch_bounds__(256) void k_agg2(const float* __restrict__ b2,
                                              float* __restrict__ out) {
    int gid = blockIdx.x * 256 + threadIdx.x;
    int node = gid >> 3;
    int l8 = threadIdx.x & 7;
    const uint2* yp2 = (const uint2*)g_y2h;    // row = 8 uint2

    uint2 sv = yp2[(size_t)node * 8 + l8];
    __half2 a0 = u2h(sv.x), a1 = u2h(sv.y);

    int e = g_rowptr[node], e1 = g_rowptr[node + 1];
    for (; e + 4 <= e1; e += 4) {
        uint2 v0 = yp2[(size_t)g_col[e]     * 8 + l8];
        uint2 v1 = yp2[(size_t)g_col[e + 1] * 8 + l8];
        uint2 v2 = yp2[(size_t)g_col[e + 2] * 8 + l8];
        uint2 v3 = yp2[(size_t)g_col[e + 3] * 8 + l8];
        a0 = __hadd2(a0, __hadd2(__hadd2(u2h(v0.x), u2h(v1.x)), __hadd2(u2h(v2.x), u2h(v3.x))));
        a1 = __hadd2(a1, __hadd2(__hadd2(u2h(v0.y), u2h(v1.y)), __hadd2(u2h(v2.y), u2h(v3.y))));
    }
    for (; e < e1; e++) {
        uint2 v = yp2[(size_t)g_col[e] * 8 + l8];
        a0 = __hadd2(a0, u2h(v.x));
        a1 = __hadd2(a1, u2h(v.y));
    }

    float dv = g_dinv[node];
    float4 bb = ((const float4*)b2)[l8];
    float2 f0 = __half22float2(a0), f1 = __half22float2(a1);
    float v0 = fmaf(dv, f0.x, bb.x);
    float v1 = fmaf(dv, f0.y, bb.y);
    float v2 = fmaf(dv, f1.x, bb.z);
    float v3 = fmaf(dv, f1.y, bb.w);

    // log_softmax over 32 classes: 4 per lane x 8 lanes
    float mx = fmaxf(fmaxf(v0, v1), fmaxf(v2, v3));
#pragma unroll
    for (int o = 4; o; o >>= 1) mx = fmaxf(mx, __shfl_xor_sync(0xffffffffu, mx, o));
    float sm = __expf(v0 - mx) + __expf(v1 - mx) + __expf(v2 - mx) + __expf(v3 - mx);
#pragma unroll
    for (int o = 4; o; o >>= 1) sm += __shfl_xor_sync(0xffffffffu, sm, o);
    float lse = mx + logf(sm);
    ((float4*)out)[(size_t)node * 8 + l8] = make_float4(v0 - lse, v1 - lse, v2 - lse, v3 - lse);
}

// ---------------- launch (5 kernels; agg1g2 at index 3 for ncu) ----------------
extern "C" void kernel_launch(void* const* d_in, const int* in_sizes, int n_in,
                              void* d_out, int out_size) {
    const float* x  = (const float*)d_in[0];
    const int*   ei = (const int*)d_in[1];
    const float* W1 = (const float*)d_in[2];
    const float* b1 = (const float*)d_in[3];
    const float* W2 = (const float*)d_in[4];
    const float* b2 = (const float*)d_in[5];
    float* out = (float*)d_out;

    k_prep  <<<NE / 256, 256>>>(ei, W1);
    k_scan  <<<64, 1024>>>();
    k_gemm1t<<<G1GRID, 256>>>(x, ei);
    k_agg1g2<<<NN * 8 / 256, 256>>>(b1, W2);
    k_agg2  <<<NN * 8 / 256, 256>>>(b2, out);
}

// round 14
// speedup vs baseline: 1.2698x; 1.0137x over previous
#include <cuda_runtime.h>
#include <cuda_fp16.h>

#define NN 65536
#define NE 1048576
#define DIN 1024
#define DH 64
#define NC 32

// ---------------- scratch (static device globals; no allocs) ----------------
// Self-cleaning per invocation: g_deg zeroed by in-gemm scan; g_flag/g_sdone/g_tile by k_prep.
__device__ int     g_is64;
__device__ int     g_tile;
__device__ int     g_sdone;
__device__ __align__(16) int   g_deg[NN];
__device__ int     g_bsum[64];
__device__ int     g_flag[64];
__device__ __align__(16) int   g_rowptr[NN + 1];
__device__ __align__(16) int   g_cursor[NN];
__device__ int     g_col[NE];
__device__ __align__(16) float g_dinv[NN];
__device__ __half2 g_y1h[(size_t)NN * 32];   // y1 = dinv*(x@W1), fp16 pairs
__device__ __half  g_y2h[(size_t)NN * NC];   // y2 = dinv*(h@W2), fp16
__device__ __half  g_w1h[DH * DIN];          // W1^T fp16: [n][k]

__device__ __forceinline__ __half2 u2h(unsigned u) { __half2 h; *(unsigned*)&h = u; return h; }

// ---------------- prep: dtype detect + degree count + W transpose + resets ----------------
__global__ void k_prep(const int* __restrict__ w, const float* __restrict__ W1) {
    int i = blockIdx.x * blockDim.x + threadIdx.x;
    int odd = w[2 * i + 1];
    int any = __syncthreads_or(odd);           // any!=0 -> int32 layout
    int d = any ? w[NE + i] : w[2 * (NE + i)];
    atomicAdd(&g_deg[d & (NN - 1)], 1);
    if (i < DIN * DH) {
        int k = i >> 6, n = i & 63;
        g_w1h[n * DIN + k] = __float2half_rn(W1[i]);
    }
    if (i < 64) g_flag[i] = 0;
    if (i == 0) { g_is64 = !any; g_sdone = 0; g_tile = 0; }
}

// ---------------- GEMM1 (HMMA fp16, ldmatrix, double-buffered, occ 3, persistent)
//                  + fused scan (blocks 0-63) + fused CSR fill ----------------
#define SAS 40

__device__ __forceinline__ unsigned smem_u32(const void* p) {
    unsigned a;
    asm("{ .reg .u64 t; cvta.to.shared.u64 t, %1; cvt.u32.u64 %0, t; }" : "=r"(a) : "l"(p));
    return a;
}
__device__ __forceinline__ void ldsm4(unsigned* r, unsigned addr) {
    asm volatile("ldmatrix.sync.aligned.m8n8.x4.shared.b16 {%0,%1,%2,%3}, [%4];"
                 : "=r"(r[0]), "=r"(r[1]), "=r"(r[2]), "=r"(r[3]) : "r"(addr));
}
__device__ __forceinline__ void mma16816(float* d, const unsigned* a, const unsigned* b) {
    asm("mma.sync.aligned.m16n8k16.row.col.f32.f16.f16.f32 "
        "{%0,%1,%2,%3}, {%4,%5,%6,%7}, {%8,%9}, {%0,%1,%2,%3};"
        : "+f"(d[0]), "+f"(d[1]), "+f"(d[2]), "+f"(d[3])
        : "r"(a[0]), "r"(a[1]), "r"(a[2]), "r"(a[3]), "r"(b[0]), "r"(b[1]));
}

#define NTILES (NN / 128)
#define G1GRID 444

__global__ __launch_bounds__(256, 3) void k_gemm1t(const float* __restrict__ A,
                                                   const int* __restrict__ w) {
    __shared__ __half Ah[2][128][SAS], Bh[2][64][SAS];
    __shared__ int s_tile;
    __shared__ int ss[256];
    __shared__ int s_pre;

    int tid = threadIdx.x;
    int b = blockIdx.x;

    // --- fused scan: blocks 0-63, 4 nodes per thread (decoupled lookback) ---
    if (b < 64) {
        int base = b * 1024 + tid * 4;
        int4 d4 = *(int4*)&g_deg[base];
        *(int4*)&g_deg[base] = make_int4(0, 0, 0, 0);   // self-clean for replay
        int s0 = d4.x, s01 = s0 + d4.y, s012 = s01 + d4.z, tot = s012 + d4.w;
        ss[tid] = tot;
        if (tid == 0) s_pre = 0;
        __syncthreads();
        for (int off = 1; off < 256; off <<= 1) {
            int v = (tid >= off) ? ss[tid - off] : 0;
            __syncthreads();
            ss[tid] += v;
            __syncthreads();
        }
        if (tid == 255) {
            g_bsum[b] = ss[255];
            __threadfence();
            atomicExch(&g_flag[b], 1);
        }
        if (tid < b) {
            while (atomicAdd(&g_flag[tid], 0) == 0) { __nanosleep(60); }
            atomicAdd(&s_pre, g_bsum[tid]);
        }
        __syncthreads();
        int excl = ss[tid] - tot + s_pre;
        *(int4*)&g_rowptr[base] = make_int4(excl, excl + s0, excl + s01, excl + s012);
        *(int4*)&g_cursor[base] = make_int4(excl, excl + s0, excl + s01, excl + s012);
        *(float4*)&g_dinv[base] = make_float4(rsqrtf((float)d4.x + 1.0f),
                                              rsqrtf((float)d4.y + 1.0f),
                                              rsqrtf((float)d4.z + 1.0f),
                                              rsqrtf((float)d4.w + 1.0f));
        if (b == 63 && tid == 255) g_rowptr[NN] = NE;
        __syncthreads();
        if (tid == 0) { __threadfence(); atomicAdd(&g_sdone, 1); }
    }

    // --- wait for scan completion (scan blocks are first-launched -> resident; no deadlock) ---
    if (tid == 0) {
        while (atomicAdd(&g_sdone, 0) < 64) { __nanosleep(100); }
    }
    __syncthreads();

    // --- fused CSR fill (grid-stride over edges) ---
    {
        int is64 = g_is64;
        for (int i = b * 256 + tid; i < NE; i += G1GRID * 256) {
            int s, d;
            if (is64) { s = w[2 * i]; d = w[2 * (NE + i)]; }
            else      { s = w[i];     d = w[NE + i]; }
            int p = atomicAdd(&g_cursor[d & (NN - 1)], 1);
            g_col[p] = s & (NN - 1);
        }
    }

    int wid = tid >> 5, lane = tid & 31;
    int wm = wid >> 1, wn = wid & 1;
    int g = lane >> 2, t = lane & 3;
    const unsigned* w1h32 = (const unsigned*)g_w1h;

    int a_lrow = (lane & 15);
    int a_lcol = (lane >> 4) * 8;
    unsigned aAddr[2][2], bAddr[2];
#pragma unroll
    for (int bu = 0; bu < 2; bu++) {
#pragma unroll
        for (int mt = 0; mt < 2; mt++) {
            int r0 = wm * 32 + mt * 16;
            aAddr[bu][mt] = smem_u32(&Ah[bu][r0 + a_lrow][a_lcol]);
        }
        bAddr[bu] = smem_u32(&Bh[bu][wn * 32 + lane][0]);
    }

    int srow = tid >> 3, skq = (tid & 7) * 4;
    int sbr  = tid >> 4, sbc = tid & 15;

    for (;;) {
        if (tid == 0) s_tile = atomicAdd(&g_tile, 1);
        __syncthreads();
        int tile = s_tile;
        if (tile >= NTILES) break;
        int blockRow = tile * 128;

        float acc[2][4][4];
#pragma unroll
        for (int mt = 0; mt < 2; mt++)
#pragma unroll
            for (int nt = 0; nt < 4; nt++)
#pragma unroll
                for (int q = 0; q < 4; q++) acc[mt][nt][q] = 0.0f;

        float4 av[4];
        unsigned bhv[4];
#pragma unroll
        for (int i = 0; i < 4; i++) {
            av[i]  = *(const float4*)(A + (size_t)(blockRow + srow + i * 32) * DIN + skq);
            bhv[i] = w1h32[(sbr + i * 16) * (DIN / 2) + sbc];
        }
#pragma unroll
        for (int i = 0; i < 4; i++) {
            __half2 h01 = __float22half2_rn(make_float2(av[i].x, av[i].y));
            __half2 h23 = __float22half2_rn(make_float2(av[i].z, av[i].w));
            *(uint2*)&Ah[0][srow + i * 32][skq] = make_uint2(*(unsigned*)&h01, *(unsigned*)&h23);
            *(unsigned*)&Bh[0][sbr + i * 16][sbc * 2] = bhv[i];
        }
        __syncthreads();

        for (int c = 0; c < 32; c++) {
            int bu = c & 1;
            if (c + 1 < 32) {
                int kt = (c + 1) * 32;
#pragma unroll
                for (int i = 0; i < 4; i++) {
                    av[i]  = *(const float4*)(A + (size_t)(blockRow + srow + i * 32) * DIN + kt + skq);
                    bhv[i] = w1h32[(sbr + i * 16) * (DIN / 2) + kt / 2 + sbc];
                }
            }

#pragma unroll
            for (int kk = 0; kk < 32; kk += 16) {
                unsigned ah[2][4], bb[2][4];
#pragma unroll
                for (int mt = 0; mt < 2; mt++)
                    ldsm4(ah[mt], aAddr[bu][mt] + kk * 2);
                ldsm4(bb[0], bAddr[bu] + kk * 2);
                ldsm4(bb[1], bAddr[bu] + (kk + 8) * 2);
#pragma unroll
                for (int mt = 0; mt < 2; mt++)
#pragma unroll
                    for (int nt = 0; nt < 4; nt++) {
                        unsigned bfr[2] = { bb[0][nt], bb[1][nt] };
                        mma16816(acc[mt][nt], ah[mt], bfr);
                    }
            }

            if (c + 1 < 32) {
#pragma unroll
                for (int i = 0; i < 4; i++) {
                    __half2 h01 = __float22half2_rn(make_float2(av[i].x, av[i].y));
                    __half2 h23 = __float22half2_rn(make_float2(av[i].z, av[i].w));
                    *(uint2*)&Ah[bu ^ 1][srow + i * 32][skq] =
                        make_uint2(*(unsigned*)&h01, *(unsigned*)&h23);
                    *(unsigned*)&Bh[bu ^ 1][sbr + i * 16][sbc * 2] = bhv[i];
                }
            }
            __syncthreads();
        }

#pragma unroll
        for (int mt = 0; mt < 2; mt++) {
            int r0 = blockRow + wm * 32 + mt * 16 + g;
            int r1 = r0 + 8;
            float d0 = g_dinv[r0], d1 = g_dinv[r1];
#pragma unroll
            for (int nt = 0; nt < 4; nt++) {
                int ci = wn * 16 + nt * 4 + t;
                g_y1h[(size_t)r0 * 32 + ci] =
                    __floats2half2_rn(acc[mt][nt][0] * d0, acc[mt][nt][1] * d0);
                g_y1h[(size_t)r1 * 32 + ci] =
                    __floats2half2_rn(acc[mt][nt][2] * d1, acc[mt][nt][3] * d1);
            }
        }
        __syncthreads();
    }
}

// ---------------- layer-1 aggregation + relu + GEMM2 fused (8 lanes per node) ----------------
__global__ __launch_bounds__(256) void k_agg1g2(const float* __restrict__ b1,
                                                const float* __restrict__ W2) {
    __shared__ float4 Ws4[DH][8];   // [k][l8] = {W2[k][l8], W2[k][l8+8], W2[k][l8+16], W2[k][l8+24]}
    for (int i = threadIdx.x; i < DH * 8; i += 256) {
        int k = i >> 3, c = i & 7;
        Ws4[k][c] = make_float4(W2[k * NC + c], W2[k * NC + c + 8],
                                W2[k * NC + c + 16], W2[k * NC + c + 24]);
    }
    __syncthreads();

    int gid = blockIdx.x * 256 + threadIdx.x;
    int node = gid >> 3;
    int l8 = threadIdx.x & 7;
    const uint4* yp4 = (const uint4*)g_y1h;    // row = 8 uint4

    uint4 sv = yp4[(size_t)node * 8 + l8];
    __half2 a0 = u2h(sv.x), a1 = u2h(sv.y), a2 = u2h(sv.z), a3 = u2h(sv.w);

    int e = g_rowptr[node], e1 = g_rowptr[node + 1];
    for (; e + 4 <= e1; e += 4) {
        uint4 v0 = yp4[(size_t)g_col[e]     * 8 + l8];
        uint4 v1 = yp4[(size_t)g_col[e + 1] * 8 + l8];
        uint4 v2 = yp4[(size_t)g_col[e + 2] * 8 + l8];
        uint4 v3 = yp4[(size_t)g_col[e + 3] * 8 + l8];
        a0 = __hadd2(a0, __hadd2(__hadd2(u2h(v0.x), u2h(v1.x)), __hadd2(u2h(v2.x), u2h(v3.x))));
        a1 = __hadd2(a1, __hadd2(__hadd2(u2h(v0.y), u2h(v1.y)), __hadd2(u2h(v2.y), u2h(v3.y))));
        a2 = __hadd2(a2, __hadd2(__hadd2(u2h(v0.z), u2h(v1.z)), __hadd2(u2h(v2.z), u2h(v3.z))));
        a3 = __hadd2(a3, __hadd2(__hadd2(u2h(v0.w), u2h(v1.w)), __hadd2(u2h(v2.w), u2h(v3.w))));
    }
    for (; e < e1; e++) {
        uint4 v = yp4[(size_t)g_col[e] * 8 + l8];
        a0 = __hadd2(a0, u2h(v.x));
        a1 = __hadd2(a1, u2h(v.y));
        a2 = __hadd2(a2, u2h(v.z));
        a3 = __hadd2(a3, u2h(v.w));
    }

    float dv = g_dinv[node];
    float4 bb0 = ((const float4*)b1)[l8 * 2];
    float4 bb1 = ((const float4*)b1)[l8 * 2 + 1];
    float2 f0 = __half22float2(a0), f1 = __half22float2(a1);
    float2 f2 = __half22float2(a2), f3 = __half22float2(a3);
    float h[8];
    h[0] = fmaxf(fmaf(dv, f0.x, bb0.x), 0.0f);
    h[1] = fmaxf(fmaf(dv, f0.y, bb0.y), 0.0f);
    h[2] = fmaxf(fmaf(dv, f1.x, bb0.z), 0.0f);
    h[3] = fmaxf(fmaf(dv, f1.y, bb0.w), 0.0f);
    h[4] = fmaxf(fmaf(dv, f2.x, bb1.x), 0.0f);
    h[5] = fmaxf(fmaf(dv, f2.y, bb1.y), 0.0f);
    h[6] = fmaxf(fmaf(dv, f3.x, bb1.z), 0.0f);
    h[7] = fmaxf(fmaf(dv, f3.y, bb1.w), 0.0f);

    // fused GEMM2 with float4-permuted W2: lane computes classes l8, l8+8, l8+16, l8+24
    float acc0 = 0.0f, acc1 = 0.0f, acc2 = 0.0f, acc3 = 0.0f;
#pragma unroll
    for (int j = 0; j < 8; j++) {
#pragma unroll
        for (int s = 0; s < 8; s++) {
            float hb = __shfl_sync(0xffffffffu, h[j], s, 8);
            float4 wv = Ws4[s * 8 + j][l8];
            acc0 = fmaf(hb, wv.x, acc0);
            acc1 = fmaf(hb, wv.y, acc1);
            acc2 = fmaf(hb, wv.z, acc2);
            acc3 = fmaf(hb, wv.w, acc3);
        }
    }
    __half* y2 = g_y2h + (size_t)node * NC;
    y2[l8]      = __float2half_rn(acc0 * dv);
    y2[l8 + 8]  = __float2half_rn(acc1 * dv);
    y2[l8 + 16] = __float2half_rn(acc2 * dv);
    y2[l8 + 24] = __float2half_rn(acc3 * dv);
}

// ---------------- layer-2 aggregation + log_softmax (8 lanes per node) ----------------
__global__ __launch_bounds__(256) void k_agg2(const float* __restrict__ b2,
                                              float* __restrict__ out) {
    int gid = blockIdx.x * 256 + threadIdx.x;
    int node = gid >> 3;
    int l8 = threadIdx.x & 7;
    const uint2* yp2 = (const uint2*)g_y2h;    // row = 8 uint2

    uint2 sv = yp2[(size_t)node * 8 + l8];
    __half2 a0 = u2h(sv.x), a1 = u2h(sv.y);

    int e = g_rowptr[node], e1 = g_rowptr[node + 1];
    for (; e + 4 <= e1; e += 4) {
        uint2 v0 = yp2[(size_t)g_col[e]     * 8 + l8];
        uint2 v1 = yp2[(size_t)g_col[e + 1] * 8 + l8];
        uint2 v2 = yp2[(size_t)g_col[e + 2] * 8 + l8];
        uint2 v3 = yp2[(size_t)g_col[e + 3] * 8 + l8];
        a0 = __hadd2(a0, __hadd2(__hadd2(u2h(v0.x), u2h(v1.x)), __hadd2(u2h(v2.x), u2h(v3.x))));
        a1 = __hadd2(a1, __hadd2(__hadd2(u2h(v0.y), u2h(v1.y)), __hadd2(u2h(v2.y), u2h(v3.y))));
    }
    for (; e < e1; e++) {
        uint2 v = yp2[(size_t)g_col[e] * 8 + l8];
        a0 = __hadd2(a0, u2h(v.x));
        a1 = __hadd2(a1, u2h(v.y));
    }

    float dv = g_dinv[node];
    float4 bb = ((const float4*)b2)[l8];
    float2 f0 = __half22float2(a0), f1 = __half22float2(a1);
    float v0 = fmaf(dv, f0.x, bb.x);
    float v1 = fmaf(dv, f0.y, bb.y);
    float v2 = fmaf(dv, f1.x, bb.z);
    float v3 = fmaf(dv, f1.y, bb.w);

    float mx = fmaxf(fmaxf(v0, v1), fmaxf(v2, v3));
#pragma unroll
    for (int o = 4; o; o >>= 1) mx = fmaxf(mx, __shfl_xor_sync(0xffffffffu, mx, o));
    float sm = __expf(v0 - mx) + __expf(v1 - mx) + __expf(v2 - mx) + __expf(v3 - mx);
#pragma unroll
    for (int o = 4; o; o >>= 1) sm += __shfl_xor_sync(0xffffffffu, sm, o);
    float lse = mx + logf(sm);
    ((float4*)out)[(size_t)node * 8 + l8] = make_float4(v0 - lse, v1 - lse, v2 - lse, v3 - lse);
}

// ---------------- launch (4 kernels) ----------------
extern "C" void kernel_launch(void* const* d_in, const int* in_sizes, int n_in,
                              void* d_out, int out_size) {
    const float* x  = (const float*)d_in[0];
    const int*   ei = (const int*)d_in[1];
    const float* W1 = (const float*)d_in[2];
    const float* b1 = (const float*)d_in[3];
    const float* W2 = (const float*)d_in[4];
    const float* b2 = (const float*)d_in[5];
    float* out = (float*)d_out;

    k_prep  <<<NE / 256, 256>>>(ei, W1);
    k_gemm1t<<<G1GRID, 256>>>(x, ei);
    k_agg1g2<<<NN * 8 / 256, 256>>>(b1, W2);
    k_agg2  <<<NN * 8 / 256, 256>>>(b2, out);
}